// round 17
// baseline (speedup 1.0000x reference)
#include <cuda_runtime.h>
#include <cuda_bf16.h>
#include <cuda_fp16.h>
#include <cstdint>
#include <cstddef>

// ---------------- instance bounds (B=16, Lmax=1984, N=24064, D=512) ----------------
#define LMAX     2048
#define SEGMAX   16
#define BMAX     64
#define NTOK_MAX 32768
#define DFIX     512

// ---- device scratch. RULE: NEVER pass these symbols as kernel args from host code —
// ---- host-side shadow address is garbage (root cause of rounds 4/6/7/8/10).
__device__ float g_S[(size_t)SEGMAX * LMAX * LMAX];   // scores fp32; after softmax each
                                                      // row starts with P[L] fp16
__device__ __half g_zhi[(size_t)NTOK_MAX * DFIX];     // h fp16 split (row-major)
__device__ __half g_zlo[(size_t)NTOK_MAX * DFIX];
__device__ __half g_yhi[(size_t)NTOK_MAX * DFIX];     // x = hW^T+b fp16 split
__device__ __half g_ylo[(size_t)NTOK_MAX * DFIX];
__device__ __half g_zThi[(size_t)DFIX * NTOK_MAX];    // h^T fp16 split (d-major)
__device__ __half g_zTlo[(size_t)DFIX * NTOK_MAX];
__device__ __half g_whi[DFIX * DFIX];
__device__ __half g_wlo[DFIX * DFIX];
__device__ int g_len[BMAX];
__device__ int g_off[BMAX];

// ---------------- helpers ----------------
__device__ __forceinline__ uint32_t smem_u32(const void* p) {
    uint32_t a;
    asm("{ .reg .u64 t; cvta.to.shared.u64 t, %1; cvt.u32.u64 %0, t; }" : "=r"(a) : "l"(p));
    return a;
}
__device__ __forceinline__ void ldsm4(uint32_t* r, uint32_t addr) {
    asm volatile("ldmatrix.sync.aligned.m8n8.x4.shared.b16 {%0,%1,%2,%3}, [%4];"
                 : "=r"(r[0]), "=r"(r[1]), "=r"(r[2]), "=r"(r[3]) : "r"(addr));
}
__device__ __forceinline__ void mma16816h(float* c, const uint32_t* a, const uint32_t* b) {
    asm volatile(
        "mma.sync.aligned.m16n8k16.row.col.f32.f16.f16.f32 "
        "{%0,%1,%2,%3}, {%4,%5,%6,%7}, {%8,%9}, {%0,%1,%2,%3};"
        : "+f"(c[0]), "+f"(c[1]), "+f"(c[2]), "+f"(c[3])
        : "r"(a[0]), "r"(a[1]), "r"(a[2]), "r"(a[3]), "r"(b[0]), "r"(b[1]));
}
__device__ __forceinline__ void split_f32h(float v, __half& hi, __half& lo) {
    hi = __float2half(v);
    lo = __float2half(v - __half2float(hi));
}

// smem: BK=16 slabs, row stride 24 elems (48 B, conflict-free ldmatrix row phases)
#define SKP 24
#define SLAB_ELEMS (128 * SKP)   // 3072 elems = 6144 B
#define SLAB_BYTES (SLAB_ELEMS * 2)

// ---------------- fp16 3-pass NT GEMM core: D = A * B^T -----------------------------
// BOTH operands pre-split (hi, lo) fp16; pure uint4 staging (8 instr/thread/slab);
// LDSM interleaved under MMAs. 256 threads = 8 warps (2m x 4n), 64x32/warp, K%16==0.
// Sources live in oversized statics: row overreads are in-bounds, feed unstored C only.
template <class Epi>
__device__ __forceinline__ void gemm_core_3p(
    const __half* __restrict__ Ahi, const __half* __restrict__ Alo, int lda,
    const __half* __restrict__ Bhi, const __half* __restrict__ Blo, int ldb,
    int K, Epi epi)
{
    __shared__ __align__(16) __half sm[2][4][SLAB_ELEMS];   // 49152 B
    const int tid  = threadIdx.x;
    const int wid  = tid >> 5, lane = tid & 31;
    const int g    = lane >> 2, tg = lane & 3;
    const int wm   = (wid >> 2) * 64;
    const int wn   = (wid & 3) * 32;
    const int lrow = lane & 15, lhalf = (lane >> 4) * 8;
    const int cr   = tid >> 1, cq = tid & 1;

    float C[4][4][4];
    #pragma unroll
    for (int i = 0; i < 4; i++)
        #pragma unroll
        for (int j = 0; j < 4; j++)
            #pragma unroll
            for (int k = 0; k < 4; k++) C[i][j][k] = 0.f;

    uint4 rah, ral, rbh, rbl;
    auto load_slab = [&](int s) {
        const int k0 = s << 4;
        rah = *(const uint4*)(Ahi + (size_t)cr * lda + k0 + cq * 8);
        ral = *(const uint4*)(Alo + (size_t)cr * lda + k0 + cq * 8);
        rbh = *(const uint4*)(Bhi + (size_t)cr * ldb + k0 + cq * 8);
        rbl = *(const uint4*)(Blo + (size_t)cr * ldb + k0 + cq * 8);
    };
    auto store_slab = [&](int buf) {
        int e = cr * SKP + cq * 8;
        *(uint4*)(&sm[buf][0][e]) = rah;
        *(uint4*)(&sm[buf][1][e]) = ral;
        *(uint4*)(&sm[buf][2][e]) = rbh;
        *(uint4*)(&sm[buf][3][e]) = rbl;
    };

    const int slabs = K >> 4;
    load_slab(0);
    store_slab(0);
    __syncthreads();

    for (int s = 0; s < slabs; s++) {
        const bool more = (s + 1 < slabs);
        if (more) load_slab(s + 1);                 // global loads overlap compute

        const uint32_t sbase = smem_u32(&sm[s & 1][0][0]);
        uint32_t ah[4][4], al[4][4], bfr[2][4], blr[2][4];
        // B frags + first A tile; remaining A tiles prefetched under MMAs
        #pragma unroll
        for (int np = 0; np < 2; np++) {
            uint32_t off = (uint32_t)((wn + np * 16 + lrow) * SKP + lhalf) * 2u;
            ldsm4(bfr[np], sbase + 2 * SLAB_BYTES + off);
            ldsm4(blr[np], sbase + 3 * SLAB_BYTES + off);
        }
        {
            uint32_t off = (uint32_t)((wm + lrow) * SKP + lhalf) * 2u;
            ldsm4(ah[0], sbase + off);
            ldsm4(al[0], sbase + SLAB_BYTES + off);
        }
        #pragma unroll
        for (int mt = 0; mt < 4; mt++) {
            if (mt < 3) {
                uint32_t off = (uint32_t)((wm + (mt + 1) * 16 + lrow) * SKP + lhalf) * 2u;
                ldsm4(ah[mt + 1], sbase + off);
                ldsm4(al[mt + 1], sbase + SLAB_BYTES + off);
            }
            #pragma unroll
            for (int nt = 0; nt < 4; nt++) {
                int np = nt >> 1, lo = nt & 1;
                uint32_t bh[2] = { bfr[np][lo], bfr[np][lo + 2] };
                uint32_t bl[2] = { blr[np][lo], blr[np][lo + 2] };
                mma16816h(C[mt][nt], ah[mt], bh);   // hi*hi
                mma16816h(C[mt][nt], ah[mt], bl);   // hi*lo
                mma16816h(C[mt][nt], al[mt], bh);   // lo*hi
            }
        }

        if (more) store_slab((s + 1) & 1);          // other buffer: safe w/o pre-sync
        __syncthreads();
    }

    #pragma unroll
    for (int mt = 0; mt < 4; mt++)
        #pragma unroll
        for (int nt = 0; nt < 4; nt++)
            epi(wm + mt * 16 + g, wn + nt * 8 + 2 * tg, C[mt][nt]);
}

// ---------------- fp16 2-pass NT GEMM core for out = P Z (R16-proven) --------------
template <class Epi>
__device__ __forceinline__ void gemm_core_pz(
    const __half* __restrict__ A, int lda,
    const __half* __restrict__ Bhi, const __half* __restrict__ Blo, int ldb,
    int K, Epi epi)
{
    __shared__ __align__(16) __half sm2[2][3][SLAB_ELEMS];   // 36864 B
    const int tid  = threadIdx.x;
    const int wid  = tid >> 5, lane = tid & 31;
    const int g    = lane >> 2, tg = lane & 3;
    const int wm   = (wid >> 2) * 64;
    const int wn   = (wid & 3) * 32;
    const int lrow = lane & 15, lhalf = (lane >> 4) * 8;
    const int cr   = tid >> 1, cq = tid & 1;

    float C[4][4][4];
    #pragma unroll
    for (int i = 0; i < 4; i++)
        #pragma unroll
        for (int j = 0; j < 4; j++)
            #pragma unroll
            for (int k = 0; k < 4; k++) C[i][j][k] = 0.f;

    uint4 rA, rbh, rbl;
    auto load_slab = [&](int s) {
        const int k0 = s << 4;
        rA  = *(const uint4*)(A   + (size_t)cr * lda + k0 + cq * 8);
        rbh = *(const uint4*)(Bhi + (size_t)cr * ldb + k0 + cq * 8);
        rbl = *(const uint4*)(Blo + (size_t)cr * ldb + k0 + cq * 8);
    };
    auto store_slab = [&](int buf) {
        int e = cr * SKP + cq * 8;
        *(uint4*)(&sm2[buf][0][e]) = rA;
        *(uint4*)(&sm2[buf][1][e]) = rbh;
        *(uint4*)(&sm2[buf][2][e]) = rbl;
    };

    const int slabs = K >> 4;
    load_slab(0);
    store_slab(0);
    __syncthreads();

    for (int s = 0; s < slabs; s++) {
        const bool more = (s + 1 < slabs);
        if (more) load_slab(s + 1);

        const uint32_t sbase = smem_u32(&sm2[s & 1][0][0]);
        uint32_t ah[4][4], bfr[2][4], blr[2][4];
        #pragma unroll
        for (int np = 0; np < 2; np++) {
            uint32_t off = (uint32_t)((wn + np * 16 + lrow) * SKP + lhalf) * 2u;
            ldsm4(bfr[np], sbase + (uint32_t)SLAB_BYTES + off);
            ldsm4(blr[np], sbase + 2u * SLAB_BYTES + off);
        }
        {
            uint32_t off = (uint32_t)((wm + lrow) * SKP + lhalf) * 2u;
            ldsm4(ah[0], sbase + off);
        }
        #pragma unroll
        for (int mt = 0; mt < 4; mt++) {
            if (mt < 3) {
                uint32_t off = (uint32_t)((wm + (mt + 1) * 16 + lrow) * SKP + lhalf) * 2u;
                ldsm4(ah[mt + 1], sbase + off);
            }
            #pragma unroll
            for (int nt = 0; nt < 4; nt++) {
                int np = nt >> 1, lo = nt & 1;
                uint32_t bh[2] = { bfr[np][lo], bfr[np][lo + 2] };
                uint32_t bl[2] = { blr[np][lo], blr[np][lo + 2] };
                mma16816h(C[mt][nt], ah[mt], bh);   // P * Z_hi
                mma16816h(C[mt][nt], ah[mt], bl);   // P * Z_lo
            }
        }

        if (more) store_slab((s + 1) & 1);
        __syncthreads();
    }

    #pragma unroll
    for (int mt = 0; mt < 4; mt++)
        #pragma unroll
        for (int nt = 0; nt < 4; nt++)
            epi(wm + mt * 16 + g, wn + nt * 8 + 2 * tg, C[mt][nt]);
}

// ---------------- offsets (int32/int64 lengths) ----------------
__global__ void offsets_kernel(const int* __restrict__ lens_raw, int count, int ntok) {
    if (threadIdx.x != 0 || blockIdx.x != 0) return;
    bool is64 = (count >= 2) && (lens_raw[1] == 0) && (lens_raw[0] != 0);
    int acc = 0;
    for (int i = 0; i < BMAX; i++) {
        int L = 0;
        if (i < count && acc < ntok) L = lens_raw[is64 ? 2 * i : i];
        if (L < 0) L = 0;
        if (L > LMAX) L = LMAX;
        g_len[i] = L; g_off[i] = acc; acc += L;
    }
}

// ---------------- split h -> g_zhi/g_zlo (fp16, row-major) ----------------
__global__ void split_z(const float* __restrict__ src, int n) {
    int i = (blockIdx.x * 256 + threadIdx.x) * 2;
    if (i >= n) return;
    float2 v = *(const float2*)(src + i);
    __half h0, l0, h1, l1;
    split_f32h(v.x, h0, l0); split_f32h(v.y, h1, l1);
    *(__half2*)(g_zhi + i) = __halves2half2(h0, h1);
    *(__half2*)(g_zlo + i) = __halves2half2(l0, l1);
}

// ---------------- split W -> g_whi/g_wlo (fp16) ----------------
__global__ void split_w(const float* __restrict__ src) {
    int i = (blockIdx.x * 256 + threadIdx.x) * 2;   // grid covers exactly DFIX*DFIX
    float2 v = *(const float2*)(src + i);
    __half h0, l0, h1, l1;
    split_f32h(v.x, h0, l0); split_f32h(v.y, h1, l1);
    *(__half2*)(g_whi + i) = __halves2half2(h0, h1);
    *(__half2*)(g_wlo + i) = __halves2half2(l0, l1);
}

// ---------------- transpose + fp16 split: h[N,512] -> zT[512, NTOK_MAX] -------------
__global__ void transpose_split(const float* __restrict__ h, int Ntok) {
    __shared__ float t[32][33];
    int d0 = blockIdx.x * 32, n0 = blockIdx.y * 32;
    for (int i = threadIdx.y; i < 32; i += 8) {
        int n = n0 + i;
        t[i][threadIdx.x] = (n < Ntok) ? h[(size_t)n * DFIX + d0 + threadIdx.x] : 0.f;
    }
    __syncthreads();
    for (int i = threadIdx.y; i < 32; i += 8) {
        int d = d0 + i, n = n0 + threadIdx.x;
        if (n >= NTOK_MAX) continue;
        float v = t[threadIdx.x][i];
        __half hi, lo; split_f32h(v, hi, lo);
        g_zThi[(size_t)d * NTOK_MAX + n] = hi;
        g_zTlo[(size_t)d * NTOK_MAX + n] = lo;
    }
}

// ---------------- GEMM 1: x = z W^T + b -> yhi/ylo (fp16 split) --------------------
__global__ __launch_bounds__(256)
void linear_gemm(const float* __restrict__ bias, int Ntok)
{
    int col0 = blockIdx.x * 128, row0 = blockIdx.y * 128;
    if (row0 >= Ntok) return;
    auto epi = [&](int gm, int gn, const float* c) {
        int gcol = col0 + gn;
        float b0 = bias[gcol], b1 = bias[gcol + 1];
        #pragma unroll
        for (int half = 0; half < 2; half++) {
            int grow = row0 + gm + half * 8;
            if (grow >= Ntok) continue;
            float f0 = c[half * 2] + b0, f1 = c[half * 2 + 1] + b1;
            __half h0, l0, h1, l1;
            split_f32h(f0, h0, l0); split_f32h(f1, h1, l1);
            size_t base = (size_t)grow * DFIX + gcol;
            *(__half2*)(g_yhi + base) = __halves2half2(h0, h1);
            *(__half2*)(g_ylo + base) = __halves2half2(l0, l1);
        }
    };
    gemm_core_3p(g_zhi + (size_t)row0 * DFIX, g_zlo + (size_t)row0 * DFIX, DFIX,
                 g_whi + (size_t)col0 * DFIX, g_wlo + (size_t)col0 * DFIX, DFIX,
                 DFIX, epi);
}

// ---------------- GEMM 2: S = Z Y^T per segment ----------------
__global__ __launch_bounds__(256)
void scores_gemm()
{
    int b = blockIdx.z;
    int L = g_len[b];
    int col0 = blockIdx.x * 128, row0 = blockIdx.y * 128;
    if (L == 0 || row0 >= L || col0 >= L) return;
    int off = g_off[b];
    int Mv = L - row0; if (Mv > 128) Mv = 128;
    int Nv = L - col0; if (Nv > 128) Nv = 128;
    float* S = g_S + (size_t)b * LMAX * LMAX;
    auto epi = [&](int gm, int gn, const float* c) {
        if (gn >= Nv) return;
        #pragma unroll
        for (int half = 0; half < 2; half++) {
            int rm = gm + half * 8;
            if (rm >= Mv) continue;
            *(float2*)(S + (size_t)(row0 + rm) * LMAX + col0 + gn) =
                make_float2(c[half * 2], c[half * 2 + 1]);
        }
    };
    gemm_core_3p(g_zhi + (size_t)(off + row0) * DFIX, g_zlo + (size_t)(off + row0) * DFIX,
                 DFIX,
                 g_yhi + (size_t)(off + col0) * DFIX, g_ylo + (size_t)(off + col0) * DFIX,
                 DFIX, DFIX, epi);
}

// ---------------- softmax: fp32 row in, fp16 P[L] out in place at row start --------
__global__ void softmax_kernel()
{
    int b = blockIdx.y, l = blockIdx.x;
    int L = g_len[b];
    if (l >= L) return;
    float* row = g_S + (size_t)b * LMAX * LMAX + (size_t)l * LMAX;
    __half* P = (__half*)row;
    int tid = threadIdx.x;

    float v[LMAX / 256];
    float mx = -1e30f;
    #pragma unroll
    for (int i = 0; i < LMAX / 256; i++) {
        int m = tid + i * 256;
        v[i] = (m < L) ? row[m] : -1e30f;
        mx = fmaxf(mx, v[i]);
    }
    __shared__ float red[256];
    red[tid] = mx; __syncthreads();
    #pragma unroll
    for (int s = 128; s > 0; s >>= 1) {
        if (tid < s) red[tid] = fmaxf(red[tid], red[tid + s]);
        __syncthreads();
    }
    mx = red[0]; __syncthreads();

    float sum = 0.f;
    #pragma unroll
    for (int i = 0; i < LMAX / 256; i++) {
        int m = tid + i * 256;
        v[i] = (m < L) ? __expf(v[i] - mx) : 0.f;
        sum += v[i];
    }
    red[tid] = sum; __syncthreads();
    #pragma unroll
    for (int s = 128; s > 0; s >>= 1) {
        if (tid < s) red[tid] += red[tid + s];
        __syncthreads();
    }
    float inv = 1.f / red[0];
    __syncthreads();   // all fp32 reads of this row precede the in-place overwrite

    #pragma unroll
    for (int i = 0; i < LMAX / 256; i++) {
        int m = tid + i * 256;
        if (m < L) P[m] = __float2half(v[i] * inv);
    }
}

// ---------------- GEMM 3: out = P Z  (fp16 2-pass core) ----------------
__global__ __launch_bounds__(256)
void out_gemm(float* __restrict__ out)
{
    int b = blockIdx.z;
    int L = g_len[b];
    int col0 = blockIdx.x * 128, row0 = blockIdx.y * 128;
    if (L == 0 || row0 >= L) return;
    int off = g_off[b];
    int Mv = L - row0; if (Mv > 128) Mv = 128;
    const __half* P = (const __half*)(g_S + (size_t)b * LMAX * LMAX)
                      + (size_t)row0 * 2 * LMAX;   // row stride 2*LMAX halves
    auto epi = [&](int gm, int gn, const float* c) {
        #pragma unroll
        for (int half = 0; half < 2; half++) {
            int rm = gm + half * 8;
            if (rm >= Mv) continue;
            *(float2*)(out + (size_t)(off + row0 + rm) * DFIX + col0 + gn) =
                make_float2(c[half * 2], c[half * 2 + 1]);
        }
    };
    gemm_core_pz(P, 2 * LMAX,
                 g_zThi + (size_t)col0 * NTOK_MAX + off,
                 g_zTlo + (size_t)col0 * NTOK_MAX + off, NTOK_MAX,
                 L /* K: multiple of 64 */, epi);
}

// ---------------- launch (NO device symbols passed as args — host shadows!) --------
extern "C" void kernel_launch(void* const* d_in, const int* in_sizes, int n_in,
                              void* d_out, int out_size)
{
    const float* h    = (const float*)d_in[0];
    const float* W    = (const float*)d_in[1];
    const float* bias = (const float*)d_in[2];
    const int*   lens = (const int*)d_in[3];

    int D    = in_sizes[2];
    int Ntok = in_sizes[0] / D;
    int B    = in_sizes[3];
    if (B > BMAX) B = BMAX;
    int Bz = B < SEGMAX ? B : SEGMAX;

    offsets_kernel<<<1, 32>>>(lens, B, Ntok);

    split_w<<<DFIX * DFIX / 512, 256>>>(W);
    int nz = Ntok * DFIX;
    split_z<<<(nz / 2 + 255) / 256, 256>>>(h, nz);
    transpose_split<<<dim3(DFIX / 32, (Ntok + 31) / 32), dim3(32, 8)>>>(h, Ntok);

    int rowTiles = (Ntok + 127) / 128;
    linear_gemm<<<dim3(DFIX / 128, rowTiles), 256>>>(bias, Ntok);

    scores_gemm<<<dim3(LMAX / 128, LMAX / 128, Bz), 256>>>();

    softmax_kernel<<<dim3(LMAX, Bz), 256>>>();

    out_gemm<<<dim3(DFIX / 128, LMAX / 128, Bz), 256>>>((float*)d_out);
}